// round 2
// baseline (speedup 1.0000x reference)
#include <cuda_runtime.h>

// Problem constants (B=4, H=8, N=2048, D=64, fp32)
#define BH   32
#define SEQ  2048
#define HD   64
#define QT   64      // q rows per block
#define KT   128     // keys per tile
#define NT   (SEQ / KT)

#define QS_STRIDE 65
#define KS_STRIDE 65
#define VS_STRIDE 68
#define PS_STRIDE 132

// Scratch: logits [BH][SEQ][SEQ] (512MB) + softmax-1 denominators.
// __device__ globals are the sanctioned scratch mechanism (no allocs allowed).
__device__ float g_L[(size_t)BH * SEQ * SEQ];
__device__ float g_sum1[BH * SEQ];

// ---------------------------------------------------------------------------
// Kernel 1: L = (Q K^T) * scale ; sum1[row] = sum_j exp(2 * L[row][j])
// Block: 256 threads (tx=tid&15, ty=tid>>4), micro-tile 4q x 8k, strided-16.
// ---------------------------------------------------------------------------
__global__ void __launch_bounds__(256) qk_kernel(
    const float* __restrict__ q, const float* __restrict__ k,
    const float* __restrict__ scale_p)
{
    extern __shared__ float sm[];
    float* Qs = sm;                        // QT * QS_STRIDE
    float* Ks = sm + QT * QS_STRIDE;       // KT * KS_STRIDE

    const float scale = *scale_p;
    const int bh = blockIdx.y;
    const int q0 = blockIdx.x * QT;
    const int tid = threadIdx.x;
    const int tx = tid & 15;
    const int ty = tid >> 4;

    // Load Q tile (64x64): 1024 float4 / 256 threads = 4 each.
    {
        const float4* qg = reinterpret_cast<const float4*>(
            q + ((size_t)bh * SEQ + q0) * HD);
        #pragma unroll
        for (int i = 0; i < 4; i++) {
            int idx = tid + 256 * i;
            int r = idx >> 4, c4 = idx & 15;
            float4 val = qg[idx];
            float* dst = Qs + r * QS_STRIDE + c4 * 4;
            dst[0] = val.x; dst[1] = val.y; dst[2] = val.z; dst[3] = val.w;
        }
    }

    float sum1p[4] = {0.f, 0.f, 0.f, 0.f};
    const float4* kg = reinterpret_cast<const float4*>(k + (size_t)bh * SEQ * HD);
    float* Lb = g_L + (size_t)bh * SEQ * SEQ;

    for (int kt = 0; kt < NT; kt++) {
        __syncthreads();   // previous tile's readers done (also covers Qs fill)
        // Load K tile (128x64): 2048 float4 / 256 = 8 each.
        #pragma unroll
        for (int i = 0; i < 8; i++) {
            int idx = tid + 256 * i;
            int r = idx >> 4, c4 = idx & 15;
            float4 val = kg[(size_t)kt * KT * (HD / 4) + idx];
            float* dst = Ks + r * KS_STRIDE + c4 * 4;
            dst[0] = val.x; dst[1] = val.y; dst[2] = val.z; dst[3] = val.w;
        }
        __syncthreads();

        float acc[4][8];
        #pragma unroll
        for (int i = 0; i < 4; i++)
            #pragma unroll
            for (int j = 0; j < 8; j++)
                acc[i][j] = 0.f;

        #pragma unroll 8
        for (int d = 0; d < HD; d++) {
            float qf[4], kf[8];
            #pragma unroll
            for (int i = 0; i < 4; i++)
                qf[i] = Qs[(ty + 16 * i) * QS_STRIDE + d];    // warp-broadcast
            #pragma unroll
            for (int j = 0; j < 8; j++)
                kf[j] = Ks[(tx + 16 * j) * KS_STRIDE + d];    // conflict-free
            #pragma unroll
            for (int i = 0; i < 4; i++)
                #pragma unroll
                for (int j = 0; j < 8; j++)
                    acc[i][j] = fmaf(qf[i], kf[j], acc[i][j]);
        }

        // Epilogue: scale, accumulate exp(2l), store logits.
        #pragma unroll
        for (int i = 0; i < 4; i++) {
            float* Lrow = Lb + (size_t)(q0 + ty + 16 * i) * SEQ + kt * KT + tx;
            #pragma unroll
            for (int j = 0; j < 8; j++) {
                float l = acc[i][j] * scale;
                sum1p[i] += __expf(2.f * l);
                Lrow[16 * j] = l;
            }
        }
    }

    // Reduce sum1 across the 16 tx-lanes sharing each row (stays in 16-groups).
    #pragma unroll
    for (int m = 8; m >= 1; m >>= 1) {
        #pragma unroll
        for (int i = 0; i < 4; i++)
            sum1p[i] += __shfl_xor_sync(0xffffffffu, sum1p[i], m);
    }
    if (tx == 0) {
        #pragma unroll
        for (int i = 0; i < 4; i++)
            g_sum1[bh * SEQ + q0 + ty + 16 * i] = sum1p[i];
    }
}

// ---------------------------------------------------------------------------
// Kernel 2: p = exp(l * exp(2l)/sum1); out = (P V) / sum(p)
// Micro-tile 4q x 4d (d cols = 4*tx..4*tx+3).
// ---------------------------------------------------------------------------
__global__ void __launch_bounds__(256) pv_kernel(
    const float* __restrict__ v, float* __restrict__ out)
{
    extern __shared__ float sm[];
    float* Ps    = sm;                                   // QT * PS_STRIDE
    float* Vs    = sm + QT * PS_STRIDE;                  // KT * VS_STRIDE
    float* inv1s = Vs + KT * VS_STRIDE;                  // QT

    const int bh = blockIdx.y;
    const int q0 = blockIdx.x * QT;
    const int tid = threadIdx.x;
    const int tx = tid & 15;
    const int ty = tid >> 4;

    if (tid < QT)
        inv1s[tid] = 1.f / g_sum1[bh * SEQ + q0 + tid];
    __syncthreads();

    float O[4][4];
    #pragma unroll
    for (int i = 0; i < 4; i++)
        #pragma unroll
        for (int c = 0; c < 4; c++)
            O[i][c] = 0.f;
    float s2p[4] = {0.f, 0.f, 0.f, 0.f};

    const float4* vg = reinterpret_cast<const float4*>(v + (size_t)bh * SEQ * HD);
    const float* Lb = g_L + (size_t)bh * SEQ * SEQ + (size_t)q0 * SEQ;

    for (int kt = 0; kt < NT; kt++) {
        // Load V tile (128x64): 8 float4 per thread, aligned stores (stride 68).
        #pragma unroll
        for (int i = 0; i < 8; i++) {
            int idx = tid + 256 * i;
            int r = idx >> 4, c4 = idx & 15;
            float4 val = vg[(size_t)kt * KT * (HD / 4) + idx];
            *reinterpret_cast<float4*>(Vs + r * VS_STRIDE + c4 * 4) = val;
        }
        // Load + transform L -> P. Thread owns rows ty+16i, cols tx*8..tx*8+7.
        #pragma unroll
        for (int i = 0; i < 4; i++) {
            int r = ty + 16 * i;
            float inv1 = inv1s[r];
            const float* Lp = Lb + (size_t)r * SEQ + kt * KT + tx * 8;
            float4 a = *reinterpret_cast<const float4*>(Lp);
            float4 b = *reinterpret_cast<const float4*>(Lp + 4);
            float lv[8] = {a.x, a.y, a.z, a.w, b.x, b.y, b.z, b.w};
            float pv[8];
            #pragma unroll
            for (int c = 0; c < 8; c++) {
                float msk = __expf(2.f * lv[c]) * inv1;   // softmax-1 weight
                float p   = __expf(lv[c] * msk);          // unnormalized softmax-2
                s2p[i] += p;
                pv[c] = p;
            }
            float* Pd = Ps + r * PS_STRIDE + tx * 8;
            *reinterpret_cast<float4*>(Pd)     = make_float4(pv[0], pv[1], pv[2], pv[3]);
            *reinterpret_cast<float4*>(Pd + 4) = make_float4(pv[4], pv[5], pv[6], pv[7]);
        }
        __syncthreads();

        // GEMM2: O += P * V over this key tile.
        #pragma unroll 4
        for (int kk = 0; kk < KT; kk++) {
            float pf[4];
            #pragma unroll
            for (int i = 0; i < 4; i++)
                pf[i] = Ps[(ty + 16 * i) * PS_STRIDE + kk];     // broadcast
            float4 vf = *reinterpret_cast<const float4*>(Vs + kk * VS_STRIDE + 4 * tx);
            #pragma unroll
            for (int i = 0; i < 4; i++) {
                O[i][0] = fmaf(pf[i], vf.x, O[i][0]);
                O[i][1] = fmaf(pf[i], vf.y, O[i][1]);
                O[i][2] = fmaf(pf[i], vf.z, O[i][2]);
                O[i][3] = fmaf(pf[i], vf.w, O[i][3]);
            }
        }
        __syncthreads();
    }

    // Reduce s2 across the 16 tx-lanes (butterfly leaves total in every lane).
    #pragma unroll
    for (int m = 8; m >= 1; m >>= 1) {
        #pragma unroll
        for (int i = 0; i < 4; i++)
            s2p[i] += __shfl_xor_sync(0xffffffffu, s2p[i], m);
    }

    #pragma unroll
    for (int i = 0; i < 4; i++) {
        float inv = 1.f / s2p[i];
        int r = q0 + ty + 16 * i;
        float4 o = make_float4(O[i][0] * inv, O[i][1] * inv,
                               O[i][2] * inv, O[i][3] * inv);
        *reinterpret_cast<float4*>(out + ((size_t)bh * SEQ + r) * HD + 4 * tx) = o;
    }
}

// ---------------------------------------------------------------------------
extern "C" void kernel_launch(void* const* d_in, const int* in_sizes, int n_in,
                              void* d_out, int out_size)
{
    const float* q     = (const float*)d_in[0];
    const float* k     = (const float*)d_in[1];
    const float* v     = (const float*)d_in[2];
    const float* scale = (const float*)d_in[3];
    float* out = (float*)d_out;

    const int smem1 = (QT * QS_STRIDE + KT * KS_STRIDE) * (int)sizeof(float);          // 49920 B
    const int smem2 = (QT * PS_STRIDE + KT * VS_STRIDE + QT) * (int)sizeof(float);     // 68864 B
    // Host-side attribute set: not a stream op, graph-capture safe, idempotent.
    cudaFuncSetAttribute(qk_kernel, cudaFuncAttributeMaxDynamicSharedMemorySize, smem1);
    cudaFuncSetAttribute(pv_kernel, cudaFuncAttributeMaxDynamicSharedMemorySize, smem2);

    dim3 grid(SEQ / QT, BH);
    qk_kernel<<<grid, 256, smem1>>>(q, k, scale);
    pv_kernel<<<grid, 256, smem2>>>(v, out);
}